// round 1
// baseline (speedup 1.0000x reference)
#include <cuda_runtime.h>
#include <math.h>

#define NB 4
#define SQ 2048
#define HD 1024
#define NH 8
#define DH 128
#define NC 1000
#define NR (NB*NH)

#define SCALE 0.088388347648318433f  // 1/sqrt(128)

// ---------------- scratch (device globals; no allocations allowed) ----------
__device__ __align__(16) float g_tmpq[NB*HD];
__device__ __align__(16) float g_q0[NB*HD];
__device__ __align__(16) float g_a[NR*HD];
__device__ __align__(16) float g_c0[NR];
__device__ __align__(16) float g_t[NR*HD];
__device__ __align__(16) float g_w[NR*SQ];      // scores, then final weights
__device__ __align__(16) float g_u[NR*HD];
__device__ __align__(16) float g_wsum[NR];
__device__ __align__(16) float g_z[NR*HD];
__device__ __align__(16) float g_attn0[NB*HD];
__device__ __align__(16) float g_res[NB*HD];
__device__ __align__(16) float g_cls[NB*HD];

__device__ __forceinline__ float warpReduceSum(float v){
    v += __shfl_xor_sync(0xffffffffu, v, 16);
    v += __shfl_xor_sync(0xffffffffu, v, 8);
    v += __shfl_xor_sync(0xffffffffu, v, 4);
    v += __shfl_xor_sync(0xffffffffu, v, 2);
    v += __shfl_xor_sync(0xffffffffu, v, 1);
    return v;
}
__device__ __forceinline__ float warpReduceMax(float v){
    v = fmaxf(v, __shfl_xor_sync(0xffffffffu, v, 16));
    v = fmaxf(v, __shfl_xor_sync(0xffffffffu, v, 8));
    v = fmaxf(v, __shfl_xor_sync(0xffffffffu, v, 4));
    v = fmaxf(v, __shfl_xor_sync(0xffffffffu, v, 2));
    v = fmaxf(v, __shfl_xor_sync(0xffffffffu, v, 1));
    return v;
}

__device__ __forceinline__ float dot4(const float4 a, const float4 b){
    return a.x*b.x + a.y*b.y + a.z*b.z + a.w*b.w;
}

// ---------------- K0: zero g_t, g_u -----------------------------------------
__global__ void k_init0(){
    int i = blockIdx.x*blockDim.x + threadIdx.x;
    if (i < NR*HD){ g_t[i] = 0.f; g_u[i] = 0.f; }
}

// ---------------- K1: tmpq[b,i] = Wq[i,:] . x[b,0,:] + bq[i] ----------------
__global__ void k_q1(const float* __restrict__ Wq, const float* __restrict__ bq,
                     const float* __restrict__ X){
    int g = blockIdx.x*(blockDim.x>>5) + (threadIdx.x>>5);
    if (g >= NB*HD) return;
    int lane = threadIdx.x & 31;
    int b = g >> 10, i = g & (HD-1);
    const float4* wv = (const float4*)(Wq + (size_t)i*HD);
    const float4* xv = (const float4*)(X + (size_t)b*SQ*HD);
    float acc = 0.f;
    #pragma unroll
    for (int k = lane; k < HD/4; k += 32) acc += dot4(wv[k], xv[k]);
    acc = warpReduceSum(acc);
    if (lane == 0) g_tmpq[g] = acc + bq[i];
}

// ---------------- K2: q0[b,i] = wiq[i,:] . tmpq[b,:] + biq[i] ---------------
__global__ void k_q2(const float* __restrict__ ipw, const float* __restrict__ ipb){
    int g = blockIdx.x*(blockDim.x>>5) + (threadIdx.x>>5);
    if (g >= NB*HD) return;
    int lane = threadIdx.x & 31;
    int b = g >> 10, i = g & (HD-1);
    const float4* wv = (const float4*)(ipw + (size_t)i*HD);   // wiq = rows [0,1024)
    const float4* xv = (const float4*)(g_tmpq + (size_t)b*HD);
    float acc = 0.f;
    #pragma unroll
    for (int k = lane; k < HD/4; k += 32) acc += dot4(wv[k], xv[k]);
    acc = warpReduceSum(acc);
    if (lane == 0) g_q0[g] = acc + ipb[i];
}

// ---------------- K3: a[r,i] = sum_j wik[h*128+j, i] * q0[b, h*128+j] -------
__global__ void k_a_kernel(const float* __restrict__ ipw){
    int r  = blockIdx.x >> 2;          // 4 blocks of 256 threads per r
    int i0 = (blockIdx.x & 3) * 256;
    int b = r / NH, h = r % NH;
    __shared__ float qs[DH];
    if (threadIdx.x < DH) qs[threadIdx.x] = g_q0[b*HD + h*DH + threadIdx.x];
    __syncthreads();
    int i = i0 + threadIdx.x;
    const float* wik = ipw + (size_t)(HD + h*DH)*HD + i;   // rows [1024,2048)
    float acc = 0.f;
    #pragma unroll 4
    for (int j = 0; j < DH; j++) acc += wik[(size_t)j*HD] * qs[j];
    g_a[r*HD + i] = acc;
}

// ---------------- K4: c0[r] = a[r,:].bk + q0_h.bik_h ------------------------
__global__ void k_c0(const float* __restrict__ bk, const float* __restrict__ ipb){
    int r = blockIdx.x; int b = r / NH, h = r % NH;
    float acc = 0.f;
    for (int i = threadIdx.x; i < HD; i += 128) acc += g_a[r*HD+i]*bk[i];
    if (threadIdx.x < DH) acc += g_q0[b*HD + h*DH + threadIdx.x] * ipb[HD + h*DH + threadIdx.x];
    acc = warpReduceSum(acc);
    __shared__ float s[4];
    if ((threadIdx.x & 31) == 0) s[threadIdx.x>>5] = acc;
    __syncthreads();
    if (threadIdx.x == 0) g_c0[r] = s[0]+s[1]+s[2]+s[3];
}

// ---------------- K5: t[r,i] += sum_m a[r,m] * Wk[m,i] (tiled, atomics) -----
__global__ void k_tgemm(const float* __restrict__ Wk){
    int i0 = blockIdx.x * 128;
    int m0 = blockIdx.y * 128;
    __shared__ float As[32][128];
    for (int idx = threadIdx.x; idx < 32*128; idx += 256){
        int r = idx >> 7, m = idx & 127;
        As[r][m] = g_a[r*HD + m0 + m];
    }
    __syncthreads();
    int tx = threadIdx.x & 127, ty = threadIdx.x >> 7;   // ty in {0,1}
    float acc[16];
    #pragma unroll
    for (int r = 0; r < 16; r++) acc[r] = 0.f;
    const float* wk = Wk + (size_t)m0*HD + i0 + tx;
    for (int mm = 0; mm < 128; mm++){
        float wv = wk[(size_t)mm*HD];
        #pragma unroll
        for (int r = 0; r < 16; r++) acc[r] += As[ty*16+r][mm]*wv;
    }
    #pragma unroll
    for (int r = 0; r < 16; r++)
        atomicAdd(&g_t[(size_t)(ty*16+r)*HD + i0 + tx], acc[r]);
}

// ---------------- K6: scores[r,key] = (t[r,:].x[b,key,:] + c0[r])*SCALE -----
__global__ void k_scores(const float* __restrict__ X, const int* __restrict__ mask){
    int key = blockIdx.x & (SQ-1);
    int b   = blockIdx.x >> 11;
    int h = threadIdx.x >> 5, lane = threadIdx.x & 31;
    const float4* xv = (const float4*)(X + ((size_t)b*SQ + key)*HD);
    const float4* tv = (const float4*)(g_t + (size_t)(b*NH + h)*HD);
    float acc = 0.f;
    #pragma unroll
    for (int k = lane; k < HD/4; k += 32) acc += dot4(xv[k], tv[k]);
    acc = warpReduceSum(acc);
    if (lane == 0){
        float s = (mask[b*SQ + key] == 0) ? -1e9f
                                          : (acc + g_c0[b*NH+h]) * SCALE;
        g_w[(size_t)(b*NH+h)*SQ + key] = s;
    }
}

// ---------------- K7: softmax + hard threshold + renorm; writes d_out tail --
__global__ void k_softmax(float* __restrict__ wout){
    int r = blockIdx.x;
    int tid = threadIdx.x;                     // 256 threads, 8 keys each
    float v[8];
    #pragma unroll
    for (int k = 0; k < 8; k++) v[k] = g_w[(size_t)r*SQ + tid + k*256];

    __shared__ float red[8];
    float m = v[0];
    #pragma unroll
    for (int k = 1; k < 8; k++) m = fmaxf(m, v[k]);
    m = warpReduceMax(m);
    if ((tid & 31) == 0) red[tid>>5] = m;
    __syncthreads();
    float mx = red[0];
    #pragma unroll
    for (int k = 1; k < 8; k++) mx = fmaxf(mx, red[k]);
    __syncthreads();

    float p[8], ls = 0.f;
    #pragma unroll
    for (int k = 0; k < 8; k++){ p[k] = expf(v[k]-mx); ls += p[k]; }
    ls = warpReduceSum(ls);
    if ((tid & 31) == 0) red[tid>>5] = ls;
    __syncthreads();
    float denom = 0.f;
    #pragma unroll
    for (int k = 0; k < 8; k++) denom += red[k];
    __syncthreads();

    float inv_d = 1.f/denom, ls2 = 0.f;
    #pragma unroll
    for (int k = 0; k < 8; k++){
        float w0 = p[k]*inv_d;
        p[k] = (w0 < 0.001f) ? 0.f : w0;       // hard threshold (strict <)
        ls2 += p[k];
    }
    ls2 = warpReduceSum(ls2);
    if ((tid & 31) == 0) red[tid>>5] = ls2;
    __syncthreads();
    float s2 = 0.f;
    #pragma unroll
    for (int k = 0; k < 8; k++) s2 += red[k];
    float inv2 = 1.f/(s2 + 1e-9f);

    #pragma unroll
    for (int k = 0; k < 8; k++){
        float wf = p[k]*inv2;
        int key = tid + k*256;
        g_w[(size_t)r*SQ + key] = wf;
        if (wout) wout[(size_t)r*SQ + key] = wf;
    }
    if (tid == 0) g_wsum[r] = s2*inv2;
}

// ---------------- K7b: z init = bv[i]*wsum[r] -------------------------------
__global__ void k_initz(const float* __restrict__ bv){
    int idx = blockIdx.x*blockDim.x + threadIdx.x;
    if (idx < NR*HD){
        int r = idx >> 10, i = idx & (HD-1);
        g_z[idx] = bv[i]*g_wsum[r];
    }
}

// ---------------- K8: u[r,i] += sum_key w[r,key]*x[b,key,i] -----------------
__global__ void k_u(const float* __restrict__ X){
    int b  = blockIdx.z;
    int i  = blockIdx.x*128 + threadIdx.x;
    int k0 = blockIdx.y*256;
    __shared__ float Ws[NH][256];
    for (int idx = threadIdx.x; idx < NH*256; idx += 128){
        int h = idx >> 8, kk = idx & 255;
        Ws[h][kk] = g_w[(size_t)(b*NH+h)*SQ + k0 + kk];
    }
    __syncthreads();
    float acc[NH];
    #pragma unroll
    for (int h = 0; h < NH; h++) acc[h] = 0.f;
    const float* xp = X + ((size_t)b*SQ + k0)*HD + i;
    for (int kk = 0; kk < 256; kk++){
        bool nz = false;
        #pragma unroll
        for (int h = 0; h < NH; h++) nz |= (Ws[h][kk] != 0.f);
        if (nz){                                   // warp-uniform: ~89% sparse
            float x = xp[(size_t)kk*HD];
            #pragma unroll
            for (int h = 0; h < NH; h++) acc[h] += Ws[h][kk]*x;
        }
    }
    #pragma unroll
    for (int h = 0; h < NH; h++)
        atomicAdd(&g_u[(size_t)(b*NH+h)*HD + i], acc[h]);
}

// ---------------- K9: z[r,i] += sum_m Wv[i,m]*u[r,m] (tiled, atomics) -------
__global__ void k_zgemm(const float* __restrict__ Wv){
    int i0 = blockIdx.x * 32;
    int m0 = blockIdx.y * 128;
    __shared__ float Wvs[32][129];
    __shared__ float Us [32][129];
    for (int idx = threadIdx.x; idx < 32*128; idx += 256){
        int rr = idx >> 7, mm = idx & 127;
        Wvs[rr][mm] = Wv[(size_t)(i0+rr)*HD + m0 + mm];
        Us [rr][mm] = g_u[(size_t)rr*HD + m0 + mm];
    }
    __syncthreads();
    int tx = threadIdx.x & 31;    // output column i0+tx
    int ty = threadIdx.x >> 5;    // rows 4*ty .. 4*ty+3
    float acc[4] = {0.f,0.f,0.f,0.f};
    for (int mm = 0; mm < 128; mm++){
        float wv = Wvs[tx][mm];
        #pragma unroll
        for (int r = 0; r < 4; r++) acc[r] += Us[ty*4+r][mm]*wv;
    }
    #pragma unroll
    for (int r = 0; r < 4; r++)
        atomicAdd(&g_z[(size_t)(ty*4+r)*HD + i0 + tx], acc[r]);
}

// ---------------- K10: attn0[b,hj] = wiv[hj,:].z[b,h,:] + biv[hj]*wsum ------
__global__ void k_attn0(const float* __restrict__ ipw, const float* __restrict__ ipb){
    int g = blockIdx.x*(blockDim.x>>5) + (threadIdx.x>>5);
    if (g >= NB*HD) return;
    int lane = threadIdx.x & 31;
    int b = g >> 10, hj = g & (HD-1), h = hj >> 7;
    const float4* wv = (const float4*)(ipw + (size_t)(2*HD + hj)*HD);  // wiv rows
    const float4* zv = (const float4*)(g_z + (size_t)(b*NH + h)*HD);
    float acc = 0.f;
    #pragma unroll
    for (int k = lane; k < HD/4; k += 32) acc += dot4(wv[k], zv[k]);
    acc = warpReduceSum(acc);
    if (lane == 0) g_attn0[g] = acc + ipb[2*HD + hj]*g_wsum[b*NH+h];
}

// ---------------- K11: res[b,i] = opw[i,:].attn0[b,:] + opb[i] + x[b,0,i] ---
__global__ void k_proj(const float* __restrict__ opw, const float* __restrict__ opb,
                       const float* __restrict__ X){
    int g = blockIdx.x*(blockDim.x>>5) + (threadIdx.x>>5);
    if (g >= NB*HD) return;
    int lane = threadIdx.x & 31;
    int b = g >> 10, i = g & (HD-1);
    const float4* wv = (const float4*)(opw + (size_t)i*HD);
    const float4* av = (const float4*)(g_attn0 + (size_t)b*HD);
    float acc = 0.f;
    #pragma unroll
    for (int k = lane; k < HD/4; k += 32) acc += dot4(wv[k], av[k]);
    acc = warpReduceSum(acc);
    if (lane == 0) g_res[g] = acc + opb[i] + X[(size_t)b*SQ*HD + i];
}

// ---------------- K12: LayerNorm over HD for row 0 of each batch ------------
__global__ void k_ln(const float* __restrict__ lng, const float* __restrict__ lnb){
    int b = blockIdx.x, tid = threadIdx.x;       // 256 threads, 4 elems each
    float v[4];
    #pragma unroll
    for (int k = 0; k < 4; k++) v[k] = g_res[b*HD + tid + k*256];
    __shared__ float red[8];
    float s = v[0]+v[1]+v[2]+v[3];
    s = warpReduceSum(s);
    if ((tid & 31) == 0) red[tid>>5] = s;
    __syncthreads();
    float mu = 0.f;
    #pragma unroll
    for (int k = 0; k < 8; k++) mu += red[k];
    mu *= (1.f/HD);
    __syncthreads();
    float q = 0.f;
    #pragma unroll
    for (int k = 0; k < 4; k++){ float d = v[k]-mu; q += d*d; }
    q = warpReduceSum(q);
    if ((tid & 31) == 0) red[tid>>5] = q;
    __syncthreads();
    float var = 0.f;
    #pragma unroll
    for (int k = 0; k < 8; k++) var += red[k];
    var *= (1.f/HD);
    float inv = rsqrtf(var + 1e-5f);
    #pragma unroll
    for (int k = 0; k < 4; k++){
        int i = tid + k*256;
        g_cls[b*HD + i] = (v[k]-mu)*inv*lng[i] + lnb[i];
    }
}

// ---------------- K13: logits[b,c] = fc_w[c,:].cls[b,:] + fc_b[c] -----------
__global__ void k_logits(const float* __restrict__ fcw, const float* __restrict__ fcb,
                         float* __restrict__ out){
    int g = blockIdx.x*(blockDim.x>>5) + (threadIdx.x>>5);
    if (g >= NB*NC) return;
    int lane = threadIdx.x & 31;
    int b = g / NC, c = g % NC;
    const float4* wv = (const float4*)(fcw + (size_t)c*HD);
    const float4* xv = (const float4*)(g_cls + (size_t)b*HD);
    float acc = 0.f;
    #pragma unroll
    for (int k = lane; k < HD/4; k += 32) acc += dot4(wv[k], xv[k]);
    acc = warpReduceSum(acc);
    if (lane == 0) out[(size_t)b*NC + c] = acc + fcb[c];
}

// ---------------------------------------------------------------------------
extern "C" void kernel_launch(void* const* d_in, const int* in_sizes, int n_in,
                              void* d_out, int out_size){
    const float* X    = (const float*)d_in[0];
    const int*   mask = (const int*)  d_in[1];
    const float* Wq   = (const float*)d_in[2];
    const float* bq   = (const float*)d_in[3];
    const float* Wk   = (const float*)d_in[4];
    const float* bk   = (const float*)d_in[5];
    const float* Wv   = (const float*)d_in[6];
    const float* bv   = (const float*)d_in[7];
    const float* ipw  = (const float*)d_in[8];
    const float* ipb  = (const float*)d_in[9];
    const float* opw  = (const float*)d_in[10];
    const float* opb  = (const float*)d_in[11];
    const float* lng  = (const float*)d_in[12];
    const float* lnb  = (const float*)d_in[13];
    const float* fcw  = (const float*)d_in[14];
    const float* fcb  = (const float*)d_in[15];
    float* out = (float*)d_out;
    float* wout = (out_size >= NC*NB + NR*SQ) ? (out + NB*NC) : nullptr;

    k_init0   <<<(NR*HD+255)/256, 256>>>();
    k_q1      <<<(NB*HD/8), 256>>>(Wq, bq, X);
    k_q2      <<<(NB*HD/8), 256>>>(ipw, ipb);
    k_a_kernel<<<NR*4, 256>>>(ipw);
    k_c0      <<<NR, 128>>>(bk, ipb);
    k_tgemm   <<<dim3(8,8), 256>>>(Wk);
    k_scores  <<<NB*SQ, 256>>>(X, mask);
    k_softmax <<<NR, 256>>>(wout);
    k_initz   <<<(NR*HD+255)/256, 256>>>(bv);
    k_u       <<<dim3(8,8,NB), 128>>>(X);
    k_zgemm   <<<dim3(32,8), 256>>>(Wv);
    k_attn0   <<<(NB*HD/8), 256>>>(ipw, ipb);
    k_proj    <<<(NB*HD/8), 256>>>(opw, opb, X);
    k_ln      <<<NB, 256>>>(lng, lnb);
    k_logits  <<<(NB*NC+7)/8, 256>>>(fcw, fcb, out);
}

// round 2
// speedup vs baseline: 1.3210x; 1.3210x over previous
#include <cuda_runtime.h>
#include <math.h>

#define G   132
#define T   256
#define NW  (G*8)
#define NB  4
#define SQ  2048
#define HD  1024
#define NH  8
#define NC  1000
#define NR  32

#define SCALE 0.088388347648318433f  // 1/sqrt(128)

// ---------------- scratch (device globals; no allocations allowed) ----------
__device__ unsigned g_barcnt = 0;
__device__ __align__(16) float g_tmpq[NB*HD];
__device__ __align__(16) float g_q0[NB*HD];
__device__ __align__(16) float g_a[NR*HD];
__device__ __align__(16) float g_c0[NR];
__device__ __align__(16) float g_t[NR*HD];
__device__ __align__(16) float g_w[NR*SQ];
__device__ __align__(16) float g_u[NR*HD];
__device__ __align__(16) float g_wsum[NR];
__device__ __align__(16) float g_z[NR*HD];
__device__ __align__(16) float g_attn0[NB*HD];
__device__ __align__(16) float g_res[NB*HD];
__device__ __align__(16) float g_cls[NB*HD];

__device__ __forceinline__ float warpReduceSum(float v){
    v += __shfl_xor_sync(0xffffffffu, v, 16);
    v += __shfl_xor_sync(0xffffffffu, v, 8);
    v += __shfl_xor_sync(0xffffffffu, v, 4);
    v += __shfl_xor_sync(0xffffffffu, v, 2);
    v += __shfl_xor_sync(0xffffffffu, v, 1);
    return v;
}
__device__ __forceinline__ float warpReduceMax(float v){
    v = fmaxf(v, __shfl_xor_sync(0xffffffffu, v, 16));
    v = fmaxf(v, __shfl_xor_sync(0xffffffffu, v, 8));
    v = fmaxf(v, __shfl_xor_sync(0xffffffffu, v, 4));
    v = fmaxf(v, __shfl_xor_sync(0xffffffffu, v, 2));
    v = fmaxf(v, __shfl_xor_sync(0xffffffffu, v, 1));
    return v;
}
__device__ __forceinline__ float dot4(const float4 a, const float4 b){
    return a.x*b.x + a.y*b.y + a.z*b.z + a.w*b.w;
}

// grid-wide barrier: monotonic counter, release-acquire via __threadfence
// (gpu-scope fence flushes/invalidates L1 so post-barrier loads refetch).
__device__ __forceinline__ void gsync(){
    __threadfence();              // release: make my writes L2-visible
    __syncthreads();
    if (threadIdx.x == 0){
        unsigned old = atomicAdd(&g_barcnt, 1u);
        unsigned target = (old / G + 1u) * G;
        while (*(volatile unsigned*)&g_barcnt < target){
            __nanosleep(40);
        }
    }
    __syncthreads();
    __threadfence();              // acquire: invalidate L1, see others' writes
}

// warp-collective dot of two 1024-float vectors (both global)
__device__ __forceinline__ float warpDot1024(const float* __restrict__ A,
                                             const float* __restrict__ B){
    const float4* a4 = (const float4*)A;
    const float4* b4 = (const float4*)B;
    int lane = threadIdx.x & 31;
    float acc = 0.f;
    #pragma unroll
    for (int k = 0; k < 8; k++)
        acc += dot4(a4[lane + 32*k], b4[lane + 32*k]);
    return warpReduceSum(acc);
}

__global__ __launch_bounds__(T, 2)
void fused_kernel(const float* __restrict__ X,   const int*   __restrict__ mask,
                  const float* __restrict__ Wq,  const float* __restrict__ bq,
                  const float* __restrict__ Wk,  const float* __restrict__ bk,
                  const float* __restrict__ Wv,  const float* __restrict__ bv,
                  const float* __restrict__ ipw, const float* __restrict__ ipb,
                  const float* __restrict__ opw, const float* __restrict__ opb,
                  const float* __restrict__ lng, const float* __restrict__ lnb,
                  const float* __restrict__ fcw, const float* __restrict__ fcb,
                  float* __restrict__ out, float* __restrict__ wout)
{
    __shared__ __align__(16) float sh[8208];
    const int tid  = threadIdx.x;
    const int blk  = blockIdx.x;
    const int lane = tid & 31;
    const int warp = tid >> 5;
    const int gw   = blk*8 + warp;      // global warp id 0..1055

    // ---------------- P0: zero accumulators + tmpq = Wq . x0 + bq ----------
    for (int i = blk*T + tid; i < NR*HD; i += G*T){ g_t[i] = 0.f; g_u[i] = 0.f; }
    for (int o = gw; o < NB*HD; o += NW){
        int b = o >> 10, i = o & (HD-1);
        float v = warpDot1024(Wq + (size_t)i*HD, X + (size_t)b*SQ*HD);
        if (lane == 0) g_tmpq[o] = v + bq[i];
    }
    gsync();

    // ---------------- P1: q0 = wiq . tmpq + biq ----------------------------
    for (int o = gw; o < NB*HD; o += NW){
        int b = o >> 10, i = o & (HD-1);
        float v = warpDot1024(ipw + (size_t)i*HD, g_tmpq + (size_t)b*HD);
        if (lane == 0) g_q0[o] = v + ipb[i];
    }
    gsync();

    // ---------------- P2: a[r,i] = sum_j wik_h[j,i] * q0_h[j] --------------
    if (blk < 128){
        int r = blk >> 2;                // 0..31, one r per 4 blocks
        int b = r >> 3, h = r & 7;
        int i = (blk & 3)*256 + tid;
        if (tid < 128) sh[tid] = g_q0[b*HD + h*128 + tid];
        __syncthreads();
        const float* wik = ipw + (size_t)(HD + h*128)*HD + i;
        float acc = 0.f;
        #pragma unroll 8
        for (int j = 0; j < 128; j++) acc += wik[(size_t)j*HD] * sh[j];
        g_a[r*HD + i] = acc;
    }
    gsync();

    // ---------------- P3: t += a . Wk (tiled) ; c0 on spare blocks ---------
    if (blk < 128){
        int it = blk >> 4, mc = blk & 15;
        int i0 = it*128, m0 = mc*64;
        for (int idx = tid; idx < NR*64; idx += T){
            int r = idx >> 6, m = idx & 63;
            sh[idx] = g_a[r*HD + m0 + m];
        }
        __syncthreads();
        int tx = tid & 127, ty = tid >> 7;     // ty in {0,1}
        float acc[16];
        #pragma unroll
        for (int q = 0; q < 16; q++) acc[q] = 0.f;
        const float* wk = Wk + (size_t)m0*HD + i0 + tx;
        for (int mm = 0; mm < 64; mm++){
            float wv = wk[(size_t)mm*HD];
            #pragma unroll
            for (int q = 0; q < 16; q++) acc[q] += sh[(ty*16+q)*64 + mm] * wv;
        }
        #pragma unroll
        for (int q = 0; q < 16; q++)
            atomicAdd(&g_t[(size_t)(ty*16+q)*HD + i0 + tx], acc[q]);
    } else {
        int r = (blk - 128)*8 + warp;          // 0..31
        int b = r >> 3, h = r & 7;
        float acc = 0.f;
        for (int i = lane; i < HD; i += 32) acc += g_a[r*HD + i] * bk[i];
        for (int j = lane; j < 128; j += 32)
            acc += g_q0[b*HD + h*128 + j] * ipb[HD + h*128 + j];
        acc = warpReduceSum(acc);
        if (lane == 0) g_c0[r] = acc;
    }
    gsync();

    // ---------------- P4: scores[r,key] = (t . x + c0)*SCALE ---------------
    {
        int b = blk / 33, rem = blk % 33;
        for (int idx = tid; idx < NH*HD; idx += T)
            sh[idx] = g_t[(size_t)(b*NH)*HD + idx];
        if (tid < NH) sh[8192 + tid] = g_c0[b*NH + tid];
        __syncthreads();
        const float4* sh4 = (const float4*)sh;
        int gww = rem*8 + warp;                // 0..263
        for (int key = gww; key < SQ; key += 264){
            const float4* x4 = (const float4*)(X + ((size_t)b*SQ + key)*HD);
            float4 xr[8];
            #pragma unroll
            for (int c = 0; c < 8; c++) xr[c] = x4[c*32 + lane];
            int mk = mask[b*SQ + key];
            #pragma unroll
            for (int h = 0; h < 8; h++){
                float acc = 0.f;
                #pragma unroll
                for (int c = 0; c < 8; c++)
                    acc += dot4(xr[c], sh4[h*256 + c*32 + lane]);
                acc = warpReduceSum(acc);
                if (lane == h)
                    g_w[(size_t)(b*NH+h)*SQ + key] =
                        (mk == 0) ? -1e9f : (acc + sh[8192 + h]) * SCALE;
            }
        }
    }
    gsync();

    // ---------------- P5: softmax + threshold + renorm ---------------------
    if (blk < NR){
        int r = blk;
        float v[8];
        #pragma unroll
        for (int k = 0; k < 8; k++) v[k] = g_w[(size_t)r*SQ + tid + k*256];

        float m = v[0];
        #pragma unroll
        for (int k = 1; k < 8; k++) m = fmaxf(m, v[k]);
        m = warpReduceMax(m);
        if (lane == 0) sh[warp] = m;
        __syncthreads();
        float mx = sh[0];
        #pragma unroll
        for (int k = 1; k < 8; k++) mx = fmaxf(mx, sh[k]);
        __syncthreads();

        float p[8], ls = 0.f;
        #pragma unroll
        for (int k = 0; k < 8; k++){ p[k] = expf(v[k]-mx); ls += p[k]; }
        ls = warpReduceSum(ls);
        if (lane == 0) sh[warp] = ls;
        __syncthreads();
        float denom = 0.f;
        #pragma unroll
        for (int k = 0; k < 8; k++) denom += sh[k];
        __syncthreads();

        float inv_d = 1.f/denom, ls2 = 0.f;
        #pragma unroll
        for (int k = 0; k < 8; k++){
            float w0 = p[k]*inv_d;
            p[k] = (w0 < 0.001f) ? 0.f : w0;
            ls2 += p[k];
        }
        ls2 = warpReduceSum(ls2);
        if (lane == 0) sh[warp] = ls2;
        __syncthreads();
        float s2 = 0.f;
        #pragma unroll
        for (int k = 0; k < 8; k++) s2 += sh[k];
        float inv2 = 1.f/(s2 + 1e-9f);

        #pragma unroll
        for (int k = 0; k < 8; k++){
            float wf = p[k]*inv2;
            int key = tid + k*256;
            g_w[(size_t)r*SQ + key] = wf;
            if (wout) wout[(size_t)r*SQ + key] = wf;
        }
        if (tid == 0) g_wsum[r] = s2*inv2;
    }
    gsync();

    // ---------------- P6: u[r,i] += sum_key w * x (sparse) -----------------
    {
        int b = blk / 33, rem = blk % 33;
        int k0  = rem*62 + (rem < 2 ? rem : 2);
        int cnt = 62 + (rem < 2 ? 1 : 0);
        for (int idx = tid; idx < 8*63; idx += T){
            int h = idx / 63, kk = idx - h*63;
            if (kk < cnt) sh[idx] = g_w[(size_t)(b*NH+h)*SQ + k0 + kk];
        }
        __syncthreads();
        float4 acc[8];
        #pragma unroll
        for (int h = 0; h < 8; h++) acc[h] = make_float4(0.f,0.f,0.f,0.f);
        const float4* Xb4 = (const float4*)(X + (size_t)b*SQ*HD);
        for (int kk = 0; kk < cnt; kk++){
            float wv[8];
            bool nz = false;
            #pragma unroll
            for (int h = 0; h < 8; h++){ wv[h] = sh[h*63 + kk]; nz |= (wv[h] != 0.f); }
            if (nz){
                float4 x = Xb4[(size_t)(k0+kk)*256 + tid];
                #pragma unroll
                for (int h = 0; h < 8; h++){
                    acc[h].x += wv[h]*x.x; acc[h].y += wv[h]*x.y;
                    acc[h].z += wv[h]*x.z; acc[h].w += wv[h]*x.w;
                }
            }
        }
        #pragma unroll
        for (int h = 0; h < 8; h++){
            float* up = &g_u[(size_t)(b*NH+h)*HD + tid*4];
            atomicAdd(up+0, acc[h].x);
            atomicAdd(up+1, acc[h].y);
            atomicAdd(up+2, acc[h].z);
            atomicAdd(up+3, acc[h].w);
        }
    }
    gsync();

    // ---------------- P7: z[r,i] = Wv[i,:] . u[r,:] + bv[i]*wsum[r] --------
    {
        int b = blk / 33, rem = blk % 33;
        for (int idx = tid; idx < NH*HD; idx += T)
            sh[idx] = g_u[(size_t)(b*NH)*HD + idx];
        if (tid < NH) sh[8192 + tid] = g_wsum[b*NH + tid];
        __syncthreads();
        const float4* sh4 = (const float4*)sh;
        int gww = rem*8 + warp;
        for (int i = gww; i < HD; i += 264){
            const float4* wv4 = (const float4*)(Wv + (size_t)i*HD);
            float4 wr[8];
            #pragma unroll
            for (int c = 0; c < 8; c++) wr[c] = wv4[c*32 + lane];
            #pragma unroll
            for (int h = 0; h < 8; h++){
                float acc = 0.f;
                #pragma unroll
                for (int c = 0; c < 8; c++)
                    acc += dot4(wr[c], sh4[h*256 + c*32 + lane]);
                acc = warpReduceSum(acc);
                if (lane == h)
                    g_z[(size_t)(b*NH+h)*HD + i] = acc + bv[i]*sh[8192 + h];
            }
        }
    }
    gsync();

    // ---------------- P8: attn0 = wiv . z + biv*wsum -----------------------
    for (int o = gw; o < NB*HD; o += NW){
        int b = o >> 10, hj = o & (HD-1), h = hj >> 7;
        float v = warpDot1024(ipw + (size_t)(2*HD + hj)*HD,
                              g_z + (size_t)(b*NH + h)*HD);
        if (lane == 0) g_attn0[o] = v + ipb[2*HD + hj]*g_wsum[b*NH + h];
    }
    gsync();

    // ---------------- P9: res = opw . attn0 + opb + x0 ---------------------
    for (int o = gw; o < NB*HD; o += NW){
        int b = o >> 10, i = o & (HD-1);
        float v = warpDot1024(opw + (size_t)i*HD, g_attn0 + (size_t)b*HD);
        if (lane == 0) g_res[o] = v + opb[i] + X[(size_t)b*SQ*HD + i];
    }
    gsync();

    // ---------------- P10: LayerNorm ---------------------------------------
    if (blk < NB){
        int b = blk;
        float v[4];
        #pragma unroll
        for (int k = 0; k < 4; k++) v[k] = g_res[b*HD + tid + k*256];
        float s = v[0]+v[1]+v[2]+v[3];
        s = warpReduceSum(s);
        if (lane == 0) sh[warp] = s;
        __syncthreads();
        float mu = 0.f;
        #pragma unroll
        for (int k = 0; k < 8; k++) mu += sh[k];
        mu *= (1.f/HD);
        __syncthreads();
        float q = 0.f;
        #pragma unroll
        for (int k = 0; k < 4; k++){ float d = v[k]-mu; q += d*d; }
        q = warpReduceSum(q);
        if (lane == 0) sh[warp] = q;
        __syncthreads();
        float var = 0.f;
        #pragma unroll
        for (int k = 0; k < 8; k++) var += sh[k];
        var *= (1.f/HD);
        float inv = rsqrtf(var + 1e-5f);
        #pragma unroll
        for (int k = 0; k < 4; k++){
            int i = tid + k*256;
            g_cls[b*HD + i] = (v[k]-mu)*inv*lng[i] + lnb[i];
        }
    }
    gsync();

    // ---------------- P11: logits = fcw . cls + fcb ------------------------
    for (int o = gw; o < NB*NC; o += NW){
        int b = o / NC, c = o % NC;
        float v = warpDot1024(fcw + (size_t)c*HD, g_cls + (size_t)b*HD);
        if (lane == 0) out[(size_t)b*NC + c] = v + fcb[c];
    }
}

// ---------------------------------------------------------------------------
extern "C" void kernel_launch(void* const* d_in, const int* in_sizes, int n_in,
                              void* d_out, int out_size){
    const float* X    = (const float*)d_in[0];
    const int*   mask = (const int*)  d_in[1];
    const float* Wq   = (const float*)d_in[2];
    const float* bq   = (const float*)d_in[3];
    const float* Wk   = (const float*)d_in[4];
    const float* bk   = (const float*)d_in[5];
    const float* Wv   = (const float*)d_in[6];
    const float* bv   = (const float*)d_in[7];
    const float* ipw  = (const float*)d_in[8];
    const float* ipb  = (const float*)d_in[9];
    const float* opw  = (const float*)d_in[10];
    const float* opb  = (const float*)d_in[11];
    const float* lng  = (const float*)d_in[12];
    const float* lnb  = (const float*)d_in[13];
    const float* fcw  = (const float*)d_in[14];
    const float* fcb  = (const float*)d_in[15];
    float* out  = (float*)d_out;
    float* wout = (out_size >= NB*NC + NR*SQ) ? (out + NB*NC) : nullptr;

    fused_kernel<<<G, T>>>(X, mask, Wq, bq, Wk, bk, Wv, bv,
                           ipw, ipb, opw, opb, lng, lnb, fcw, fcb,
                           out, wout);
}